// round 1
// baseline (speedup 1.0000x reference)
#include <cuda_runtime.h>
#include <math.h>

#define NSWEEPS 8
#define N 64
#define NPAIR 32
#define THREADS 256

// One CTA per 64x64 SPD matrix. Two-sided cyclic Jacobi with round-robin
// (circle method) pairing: 63 rounds/sweep, 32 disjoint rotations/round.
// A <- G^T A G accumulated into V (V columns = eigenvectors), then
// out = V diag(log diag(A)) V^T.
__global__ __launch_bounds__(THREADS, 6)
void logeig_jacobi_kernel(const float* __restrict__ x,
                          float* __restrict__ out) {
    __shared__ float A[N][N + 1];   // padded: bank-conflict-free row & col phases
    __shared__ float V[N][N + 1];
    __shared__ float cs_c[NPAIR], cs_s[NPAIR];
    __shared__ int   pp[NPAIR], qq[NPAIR];
    __shared__ float lw[N];

    const int b   = blockIdx.x;
    const int tid = threadIdx.x;
    const float* __restrict__ xin = x + (size_t)b * (N * N);
    float* __restrict__ o         = out + (size_t)b * (N * N);

    // Load A (input is symmetric SPD), init V = I.
    #pragma unroll
    for (int it = 0; it < (N * N) / THREADS; ++it) {
        int idx = tid + it * THREADS;
        int i = idx >> 6, j = idx & 63;
        A[i][j] = xin[idx];
        V[i][j] = (i == j) ? 1.0f : 0.0f;
    }
    __syncthreads();

    for (int sweep = 0; sweep < NSWEEPS; ++sweep) {
        for (int r = 0; r < N - 1; ++r) {
            // --- rotation setup: circle-method pairing + sym.schur2 ---
            if (tid < NPAIR) {
                int k = tid;
                int p, q;
                if (k == 0) {
                    p = N - 1;
                    q = r % (N - 1);
                } else {
                    p = (r + k) % (N - 1);
                    q = (r + (N - 1) - k) % (N - 1);
                }
                float app = A[p][p], aqq = A[q][q], apq = A[p][q];
                float c = 1.0f, s = 0.0f;
                if (fabsf(apq) > 1e-30f) {
                    float theta = 0.5f * (aqq - app) / apq;
                    // t = sign(theta)/(|theta| + sqrt(1+theta^2))
                    float t = copysignf(1.0f, theta) /
                              (fabsf(theta) + sqrtf(fmaf(theta, theta, 1.0f)));
                    c = rsqrtf(fmaf(t, t, 1.0f));
                    s = t * c;
                }
                pp[k] = p; qq[k] = q;
                cs_c[k] = c; cs_s[k] = s;
            }
            __syncthreads();

            // --- row phase: A <- G^T A (32 pairs x 64 cols = 2048 items) ---
            #pragma unroll
            for (int it = 0; it < (NPAIR * N) / THREADS; ++it) {
                int idx = tid + it * THREADS;
                int k = idx >> 6, j = idx & 63;
                int p = pp[k], q = qq[k];
                float c = cs_c[k], s = cs_s[k];
                float ap = A[p][j], aq = A[q][j];
                A[p][j] = fmaf(c, ap, -s * aq);
                A[q][j] = fmaf(s, ap,  c * aq);
            }
            __syncthreads();

            // --- col phase: A <- A G, and V <- V G (4096 items) ---
            #pragma unroll
            for (int it = 0; it < (2 * NPAIR * N) / THREADS; ++it) {
                int idx = tid + it * THREADS;
                int k = (idx >> 6) & (NPAIR - 1);
                int i = idx & 63;
                int p = pp[k], q = qq[k];
                float c = cs_c[k], s = cs_s[k];
                if (idx < NPAIR * N) {
                    float aip = A[i][p], aiq = A[i][q];
                    A[i][p] = fmaf(c, aip, -s * aiq);
                    A[i][q] = fmaf(s, aip,  c * aiq);
                } else {
                    float vip = V[i][p], viq = V[i][q];
                    V[i][p] = fmaf(c, vip, -s * viq);
                    V[i][q] = fmaf(s, vip,  c * viq);
                }
            }
            __syncthreads();
        }
    }

    // log of eigenvalues (diagonal of converged A)
    if (tid < N) lw[tid] = logf(fmaxf(A[tid][tid], 1e-30f));
    __syncthreads();

    // W[i][k] = V[i][k] * log(lambda_k)  (overwrite A with W)
    #pragma unroll
    for (int it = 0; it < (N * N) / THREADS; ++it) {
        int idx = tid + it * THREADS;
        int i = idx >> 6, k = idx & 63;
        A[i][k] = V[i][k] * lw[k];
    }
    __syncthreads();

    // out = W * V^T   (out[i][j] = sum_k W[i][k] * V[j][k])
    #pragma unroll
    for (int it = 0; it < (N * N) / THREADS; ++it) {
        int idx = tid + it * THREADS;
        int i = idx >> 6, j = idx & 63;
        float acc = 0.0f;
        #pragma unroll 16
        for (int k = 0; k < N; ++k)
            acc = fmaf(A[i][k], V[j][k], acc);
        o[idx] = acc;
    }
}

extern "C" void kernel_launch(void* const* d_in, const int* in_sizes, int n_in,
                              void* d_out, int out_size) {
    const float* x = (const float*)d_in[0];
    float* out = (float*)d_out;
    int B = in_sizes[0] / (N * N);   // 8192
    logeig_jacobi_kernel<<<B, THREADS>>>(x, out);
}

// round 2
// speedup vs baseline: 1.8037x; 1.8037x over previous
#include <cuda_runtime.h>
#include <math.h>

#define NSWEEPS 8
#define N 64
#define NH 32
#define FULLMASK 0xffffffffu

// One WARP per 64x64 SPD matrix. A lives in registers: lane owns column-slots
// (lane) -> top[64] and (32+lane) -> bot[64]; arrays indexed by row-slot.
// Pairs are always (slot t, slot 32+t). Tournament realized by physically
// permuting columns across lanes (shfl ring) and row-slots via a static
// 63-cycle register relabel (in-place carry walk). V (eigenvectors) lives in
// shared, addressed through per-lane original-column ids that follow the same
// permutation. out = V diag(log lambda) V^T.
__global__ void __launch_bounds__(32)
logeig_warp_kernel(const float* __restrict__ x, float* __restrict__ out)
{
    __shared__ float V[N][N + 1];
    __shared__ float lw[N];

    const int lane = threadIdx.x;
    const size_t base = (size_t)blockIdx.x * (N * N);
    const float* __restrict__ xin = x + base;
    float* __restrict__ o = out + base;

    float top[N], bot[N];

    // Load A columns (coalesced: per j, lanes cover 128B + 128B)
    #pragma unroll
    for (int j = 0; j < N; ++j) {
        top[j] = xin[j * N + lane];
        bot[j] = xin[j * N + NH + lane];
    }
    // V = I
    #pragma unroll
    for (int i = 0; i < N; ++i) {
        V[i][lane]      = (i == lane)      ? 1.0f : 0.0f;
        V[i][NH + lane] = (i == NH + lane) ? 1.0f : 0.0f;
    }
    int idt = lane;        // original column id sitting in slot (lane)
    int idb = NH + lane;   // original column id sitting in slot (32+lane)
    __syncwarp();

    for (int round = 0; round < NSWEEPS * (N - 1); ++round) {
        // ---- extract own pair's 2x2 block (static-index predicated selects)
        float app = 1.0f, apq = 0.0f, aqq = 1.0f;
        #pragma unroll
        for (int u = 0; u < NH; ++u) {
            bool m = (u == lane);
            app = m ? top[u]      : app;
            apq = m ? top[NH + u] : apq;
            aqq = m ? bot[NH + u] : aqq;
        }
        // ---- Jacobi rotation parameters (sym.schur2)
        float c = 1.0f, s = 0.0f;
        if (fabsf(apq) > 1e-30f) {
            float theta = 0.5f * (aqq - app) / apq;
            float t = copysignf(1.0f, theta) /
                      (fabsf(theta) + sqrtf(fmaf(theta, theta, 1.0f)));
            c = rsqrtf(fmaf(t, t, 1.0f));
            s = t * c;
        }

        // ---- row phase: A <- G^T A; rotate row-slot pairs (u, 32+u) of both
        //      owned columns, with every pair's (c,s) broadcast via shfl
        #pragma unroll
        for (int u = 0; u < NH; ++u) {
            float cu = __shfl_sync(FULLMASK, c, u);
            float su = __shfl_sync(FULLMASK, s, u);
            float a0 = top[u], b0 = top[NH + u];
            top[u]      = fmaf(cu, a0, -su * b0);
            top[NH + u] = fmaf(su, a0,  cu * b0);
            float a1 = bot[u], b1 = bot[NH + u];
            bot[u]      = fmaf(cu, a1, -su * b1);
            bot[NH + u] = fmaf(su, a1,  cu * b1);
        }

        // ---- V <- V G : rotate the two owned V columns (shared memory)
        #pragma unroll 8
        for (int i = 0; i < N; ++i) {
            float vp = V[i][idt], vq = V[i][idb];
            V[i][idt] = fmaf(c, vp, -s * vq);
            V[i][idb] = fmaf(s, vp,  c * vq);
        }

        // ---- col phase (A <- A G) fused with the tournament permutation.
        // moved(j): rotate elem j of the owned column pair, then ring-shift
        // across lanes:
        //   new_top[t] = t==0 ? old_top[0] : (t==1 ? old_bot[0] : old_top[t-1])
        //   new_bot[t] = t==31 ? old_top[31] : old_bot[t+1]
        // Row-slots relabel by sigma: 0->0; t->t+1 (1<=t<=30); 31->63;
        // 32->1; (32+t)->(31+t) (1<=t<=31). Applied in place via the 63-cycle
        // seq = [32, 1..31, 63..33] with one carry pair.

        // fixed row-slot 0:
        {
            float ap = top[0], aq = bot[0];
            float rt_ = fmaf(c, ap, -s * aq);
            float rb_ = fmaf(s, ap,  c * aq);
            float tsel = (lane == 0) ? rb_ : rt_;
            float tup  = __shfl_up_sync(FULLMASK, tsel, 1);
            float ntv  = (lane == 0) ? rt_ : tup;
            float bdn  = __shfl_down_sync(FULLMASK, rb_, 1);
            float nbv  = (lane == 31) ? rt_ : bdn;
            top[0] = ntv;
            bot[0] = nbv;
        }
        // carry walk along the 63-cycle:
        float ct, cb;
        {
            float ap = top[32], aq = bot[32];
            float rt_ = fmaf(c, ap, -s * aq);
            float rb_ = fmaf(s, ap,  c * aq);
            float tsel = (lane == 0) ? rb_ : rt_;
            float tup  = __shfl_up_sync(FULLMASK, tsel, 1);
            ct = (lane == 0) ? rt_ : tup;
            float bdn  = __shfl_down_sync(FULLMASK, rb_, 1);
            cb = (lane == 31) ? rt_ : bdn;
        }
        #pragma unroll
        for (int k = 1; k <= 62; ++k) {
            const int j = (k <= 31) ? k : (95 - k);   // seq[k]
            float ap = top[j], aq = bot[j];
            float rt_ = fmaf(c, ap, -s * aq);
            float rb_ = fmaf(s, ap,  c * aq);
            float tsel = (lane == 0) ? rb_ : rt_;
            float tup  = __shfl_up_sync(FULLMASK, tsel, 1);
            float ntv  = (lane == 0) ? rt_ : tup;
            float bdn  = __shfl_down_sync(FULLMASK, rb_, 1);
            float nbv  = (lane == 31) ? rt_ : bdn;
            top[j] = ct;  bot[j] = cb;   // new[seq[k]] = moved(seq[k-1])
            ct = ntv;     cb = nbv;
        }
        top[32] = ct;  bot[32] = cb;     // new[seq[0]] = moved(seq[62])

        // ---- id map follows the exact same column movement
        {
            int tsel = (lane == 0) ? idb : idt;
            int tup  = __shfl_up_sync(FULLMASK, tsel, 1);
            int nidt = (lane == 0) ? idt : tup;
            int bdn  = __shfl_down_sync(FULLMASK, idb, 1);
            int nidb = (lane == 31) ? idt : bdn;
            idt = nidt;  idb = nidb;
        }
        __syncwarp();   // V columns change ownership across rounds
    }

    // ---- eigenvalues = diagonal of converged A; publish log(lambda)
    {
        float app = 1.0f, aqq = 1.0f;
        #pragma unroll
        for (int u = 0; u < NH; ++u) {
            bool m = (u == lane);
            app = m ? top[u]      : app;
            aqq = m ? bot[NH + u] : aqq;
        }
        lw[idt] = logf(fmaxf(app, 1e-30f));
        lw[idb] = logf(fmaxf(aqq, 1e-30f));
    }
    __syncwarp();

    // ---- out = V diag(lw) V^T ; lane computes output columns (2*lane, 2*lane+1)
    //      (out is symmetric: column j == row j, stored coalesced as columns)
    #pragma unroll
    for (int i = 0; i < N; ++i) { top[i] = 0.0f; bot[i] = 0.0f; }
    const int j0 = 2 * lane, j1 = 2 * lane + 1;
    for (int k = 0; k < N; ++k) {
        float w  = lw[k];
        float w0 = w * V[j0][k];
        float w1 = w * V[j1][k];
        #pragma unroll
        for (int i = 0; i < N; ++i) {
            float v = V[i][k];          // broadcast load
            top[i] = fmaf(w0, v, top[i]);
            bot[i] = fmaf(w1, v, bot[i]);
        }
    }
    #pragma unroll
    for (int i = 0; i < N; ++i) {
        float2 val = make_float2(top[i], bot[i]);
        *reinterpret_cast<float2*>(o + i * N + j0) = val;   // coalesced
    }
}

extern "C" void kernel_launch(void* const* d_in, const int* in_sizes, int n_in,
                              void* d_out, int out_size) {
    const float* x = (const float*)d_in[0];
    float* out = (float*)d_out;
    int B = in_sizes[0] / (N * N);   // 8192
    logeig_warp_kernel<<<B, 32>>>(x, out);
}

// round 7
// speedup vs baseline: 3.0694x; 1.7017x over previous
#include <cuda_runtime.h>
#include <math.h>

#define NSWEEPS 16
#define N 64
#define NH 32
#define NP 32            // packed row-pairs per column
#define FULLMASK 0xffffffffu

typedef unsigned long long ull;

__device__ __forceinline__ ull pack2(float lo, float hi) {
    ull r; asm("mov.b64 %0, {%1, %2};" : "=l"(r) : "f"(lo), "f"(hi)); return r;
}
__device__ __forceinline__ void unpack2(ull v, float& lo, float& hi) {
    asm("mov.b64 {%0, %1}, %2;" : "=f"(lo), "=f"(hi) : "l"(v));
}
__device__ __forceinline__ ull fma2(ull a, ull b, ull c) {
    ull d; asm("fma.rn.f32x2 %0, %1, %2, %3;" : "=l"(d) : "l"(a), "l"(b), "l"(c));
    return d;
}
__device__ __forceinline__ ull mul2(ull a, ull b) {
    ull d; asm("mul.rn.f32x2 %0, %1, %2;" : "=l"(d) : "l"(a), "l"(b));
    return d;
}
__device__ __forceinline__ float hsum2(ull v) {
    float lo, hi; unpack2(v, lo, hi); return lo + hi;
}

// One WARP per 64x64 SPD matrix. One-sided Jacobi on the columns of A.
// 16 sweeps: one-sided == two-sided on the Gram A^2, whose small-eigenvalue
// cluster needs more sweeps to resolve internally than A itself (the log
// amplifies any unresolved small-lambda subspace into O(1) error).
// Fresh 2x2 Gram each round; circle-method ring tournament (verified complete);
//   log(A) = sum_k (log lambda_k / lambda_k^2) u_k u_k^T,  lambda_k^2 = |u_k|^2.
__global__ void __launch_bounds__(32, 12)
logeig_onesided_kernel(const float* __restrict__ x, float* __restrict__ out)
{
    __shared__ float U[N][N + 1];
    __shared__ float w[N];

    const int lane = threadIdx.x;
    const size_t base = (size_t)blockIdx.x * (N * N);
    const float* __restrict__ xin = x + base;
    float* __restrict__ o = out + base;

    ull top2[NP], bot2[NP];   // columns in slots (lane) and (32+lane)

    // Load: top2[j] packs rows (2j, 2j+1) of column `lane`
    #pragma unroll
    for (int j = 0; j < NP; ++j) {
        top2[j] = pack2(xin[(2 * j) * N + lane],      xin[(2 * j + 1) * N + lane]);
        bot2[j] = pack2(xin[(2 * j) * N + NH + lane], xin[(2 * j + 1) * N + NH + lane]);
    }

    for (int round = 0; round < NSWEEPS * (N - 1); ++round) {
        // ---- fresh 2x2 Gram block of the owned pair (fused 3-dot)
        ull sp = 0ull, sx = 0ull, sq = 0ull;
        #pragma unroll
        for (int j = 0; j < NP; ++j) {
            ull t2 = top2[j], b2 = bot2[j];
            sp = fma2(t2, t2, sp);
            sx = fma2(t2, b2, sx);
            sq = fma2(b2, b2, sq);
        }
        float app = hsum2(sp);
        float apq = hsum2(sx);
        float aqq = hsum2(sq);

        // ---- Jacobi rotation from the Gram block
        float c = 1.0f, s = 0.0f;
        if (fabsf(apq) > 1e-30f) {
            float theta = 0.5f * (aqq - app) / apq;
            float t = copysignf(1.0f, theta) /
                      (fabsf(theta) + sqrtf(fmaf(theta, theta, 1.0f)));
            c = rsqrtf(fmaf(t, t, 1.0f));
            s = t * c;
        }
        const ull cc = pack2(c, c);
        const ull ss = pack2(s, s);
        const ull ns = pack2(-s, -s);

        // ---- rotate the column pair and ring-shift columns across lanes
        // (circle-method tournament, fused). Rows never move.
        #pragma unroll
        for (int j = 0; j < NP; ++j) {
            ull t2 = top2[j], b2 = bot2[j];
            ull rt = fma2(cc, t2, mul2(ns, b2));    // c*top - s*bot
            ull rb = fma2(ss, t2, mul2(cc, b2));    // s*top + c*bot
            ull tsel = (lane == 0) ? rb : rt;
            ull tup  = __shfl_up_sync(FULLMASK, tsel, 1);
            top2[j]  = (lane == 0) ? rt : tup;
            ull bdn  = __shfl_down_sync(FULLMASK, rb, 1);
            bot2[j]  = (lane == 31) ? rt : bdn;
        }
    }

    // ---- final fresh squared norms -> weights w = log(lambda)/lambda^2
    {
        ull sp = 0ull, sq = 0ull;
        #pragma unroll
        for (int j = 0; j < NP; ++j) {
            sp = fma2(top2[j], top2[j], sp);
            sq = fma2(bot2[j], bot2[j], sq);
        }
        float nt = hsum2(sp);
        float nb = hsum2(sq);
        w[lane]      = 0.5f * logf(fmaxf(nt, 1e-38f)) / nt;
        w[NH + lane] = 0.5f * logf(fmaxf(nb, 1e-38f)) / nb;
    }

    // ---- publish U to shared
    #pragma unroll
    for (int j = 0; j < NP; ++j) {
        float a0, a1, b0, b1;
        unpack2(top2[j], a0, a1);
        unpack2(bot2[j], b0, b1);
        U[2 * j][lane]          = a0;
        U[2 * j + 1][lane]      = a1;
        U[2 * j][NH + lane]     = b0;
        U[2 * j + 1][NH + lane] = b1;
    }
    __syncwarp();

    // ---- out = sum_k w_k u_k u_k^T ; lane computes output columns
    //      j0 = 2*lane, j0+1; accumulators reuse top2/bot2
    #pragma unroll
    for (int j = 0; j < NP; ++j) { top2[j] = 0ull; bot2[j] = 0ull; }
    const int j0 = 2 * lane;
    for (int k = 0; k < N; ++k) {
        float wk = w[k];
        float a0 = wk * U[j0][k];
        float a1 = wk * U[j0 + 1][k];
        ull aa0 = pack2(a0, a0);
        ull aa1 = pack2(a1, a1);
        #pragma unroll
        for (int j = 0; j < NP; ++j) {
            ull vv = pack2(U[2 * j][k], U[2 * j + 1][k]);   // broadcast loads
            top2[j] = fma2(aa0, vv, top2[j]);
            bot2[j] = fma2(aa1, vv, bot2[j]);
        }
    }
    // rows 2j / 2j+1, columns (j0, j0+1) contiguous -> coalesced float2 stores
    #pragma unroll
    for (int j = 0; j < NP; ++j) {
        float t0, t1, b0, b1;
        unpack2(top2[j], t0, t1);
        unpack2(bot2[j], b0, b1);
        *reinterpret_cast<float2*>(o + (2 * j) * N + j0)     = make_float2(t0, b0);
        *reinterpret_cast<float2*>(o + (2 * j + 1) * N + j0) = make_float2(t1, b1);
    }
}

extern "C" void kernel_launch(void* const* d_in, const int* in_sizes, int n_in,
                              void* d_out, int out_size) {
    const float* x = (const float*)d_in[0];
    float* out = (float*)d_out;
    int B = in_sizes[0] / (N * N);   // 8192
    logeig_onesided_kernel<<<B, 32>>>(x, out);
}